// round 3
// baseline (speedup 1.0000x reference)
#include <cuda_runtime.h>
#include <math.h>

#define NT1 512

// Scratch (static device arrays — no allocation)
__device__ float2 g_state[32u * 65536u];   // 16 MB: [b][k][b0][b15][idx14]
__device__ float  g_xd[256];               // pooled inputs: [b][16]
__device__ float  g_feats[16 * 24];        // quantum features

struct K2Args {
    unsigned sbits[12];     // 16-bit sign pattern over group index e
    unsigned outer14[12];   // parity mask over idx14 bits 3..13 (wires 1..11)
    unsigned w0f[12];       // does mask include wire 0?
};

__device__ __forceinline__ int sphys(int idx) { return idx ^ ((idx >> 5) & 0xF); }

template<int T, int N>
__device__ __forceinline__ void ryg(float2* a, float c, float s) {
#pragma unroll
    for (int m = 0; m < N; m++) {
        if (m & (1 << T)) continue;
        int u = m, v = m | (1 << T);
        float2 au = a[u], av = a[v];
        a[u].x = c * au.x - s * av.x;  a[u].y = c * au.y - s * av.y;
        a[v].x = s * au.x + c * av.x;  a[v].y = s * au.y + c * av.y;
    }
}
template<int T, int N>
__device__ __forceinline__ void rxg(float2* a, float c, float s) {
#pragma unroll
    for (int m = 0; m < N; m++) {
        if (m & (1 << T)) continue;
        int u = m, v = m | (1 << T);
        float2 au = a[u], av = a[v];
        // RX: [[c, -is],[-is, c]]
        a[u].x = c * au.x + s * av.y;  a[u].y = c * au.y - s * av.x;
        a[v].x = c * av.x + s * au.y;  a[v].y = c * av.y - s * au.x;
    }
}
template<int C, int T, int N>
__device__ __forceinline__ void cng(float2* a) {
#pragma unroll
    for (int m = 0; m < N; m++) {
        if (!(m & (1 << C)) || (m & (1 << T))) continue;
        int v = m | (1 << T);
        float2 t = a[m]; a[m] = a[v]; a[v] = t;
    }
}

// ---------------- kernel 0: 7x7 avg pooling -> g_xd ----------------
extern "C" __global__ void qsim_k0(const float* __restrict__ x) {
    int t = threadIdx.x;            // 256 threads: b*16 + cell
    int b = t >> 4, cell = t & 15;
    int r = cell >> 2, c = cell & 3;
    const float* px = x + b * 784 + r * 7 * 28 + c * 7;
    float s = 0.f;
    for (int u = 0; u < 7; u++)
#pragma unroll
        for (int v = 0; v < 7; v++) s += px[u * 28 + v];
    g_xd[t] = s * (1.f / 49.f);
}

// ---------------- kernel 1: 14-qubit smem-resident simulation ----------------
// 128 blocks: bi = ((b*2 + k)*2 + b0)*2 + b15. Each holds the 2^14-amp
// sub-statevector (wire0/wire15 bits fixed) and runs the conv block up to
// (but excluding) CNOT(12,15) of iteration 11.
extern "C" __global__ void __launch_bounds__(NT1) qsim_k1(const float* __restrict__ kp) {
    extern __shared__ float2 S[];        // 16384 amps (XOR-swizzled layout)
    __shared__ float tws[16][2];
    __shared__ float ptrig[5][2];
    int tid = threadIdx.x;
    int bi = blockIdx.x;
    int b = bi >> 3, k = (bi >> 2) & 1, bb0 = (bi >> 1) & 1, bb15 = bi & 1;

    if (tid < 16) {
        float ang = g_xd[b * 16 + tid];
        if (tid == 0) ang += kp[k * 5];      // fold iter-0 RY(p0) into encoder on wire 0
        float h = 0.5f * ang;
        tws[tid][0] = cosf(h); tws[tid][1] = sinf(h);
    }
    if (tid < 5) {
        float h = 0.5f * kp[k * 5 + tid];
        ptrig[tid][0] = cosf(h); ptrig[tid][1] = sinf(h);
    }
    __syncthreads();

    float c0 = ptrig[0][0], s0 = ptrig[0][1];
    float c1 = ptrig[1][0], s1 = ptrig[1][1];
    float c2 = ptrig[2][0], s2 = ptrig[2][1];
    float c3 = ptrig[3][0], s3 = ptrig[3][1];
    float c4 = ptrig[4][0], s4 = ptrig[4][1];

    // ---- init: product state (encoder folded; CNOT(0,3) folded as table swap) ----
    {
        float A = tws[0][bb0] * tws[15][bb15];
        float tc[14], ts[14];
#pragma unroll
        for (int w = 1; w <= 14; ++w) { tc[w - 1] = tws[w][0]; ts[w - 1] = tws[w][1]; }
        if (bb0) { float t = tc[2]; tc[2] = ts[2]; ts[2] = t; }   // X on wire 3 when wire0==1
        for (int j = tid; j < 16384; j += NT1) {
            float p = A;
#pragma unroll
            for (int w = 1; w <= 14; ++w)
                p *= ((j >> (14 - w)) & 1) ? ts[w - 1] : tc[w - 1];
            S[sphys(j)] = make_float2(p, 0.f);
        }
    }
    __syncthreads();

    // ---- iteration 0 (wires 1,3,4 local; wire-0 ops folded) ----
    for (int g = tid; g < 2048; g += NT1) {
        const int mask = (1 << 13) | (1 << 11) | (1 << 10);
        int base = 0, gg = g;
#pragma unroll
        for (int bit = 0; bit < 14; ++bit)
            if (!((mask >> bit) & 1)) { base |= (gg & 1) << bit; gg >>= 1; }
        int off[8]; float2 a[8];
#pragma unroll
        for (int e = 0; e < 8; e++) {
            int idx = base | (((e >> 2) & 1) << 13) | (((e >> 1) & 1) << 11) | ((e & 1) << 10);
            off[e] = sphys(idx); a[e] = S[off[e]];
        }
        ryg<1, 8>(a, c1, s1);     // RY(p1) wire 3
        ryg<2, 8>(a, c2, s2);     // RY(p2) wire 1
        cng<2, 0, 8>(a);          // CNOT(1,4)
        cng<1, 2, 8>(a);          // CNOT(3,1)
        rxg<0, 8>(a, c3, s3);     // RX(p3) wire 4
        rxg<2, 8>(a, c4, s4);     // RX(p4) wire 1
#pragma unroll
        for (int e = 0; e < 8; e++) S[off[e]] = a[e];
    }
    __syncthreads();

    // ---- iterations 1..10 (generic 4-bit group: wires i,i+1,i+3,i+4) ----
    for (int i = 1; i <= 10; i++) {
        int B3 = 14 - i, B2 = 13 - i, B1 = 11 - i, B0 = 10 - i;
        int mask = (1 << B3) | (1 << B2) | (1 << B1) | (1 << B0);
        for (int g = tid; g < 1024; g += NT1) {
            int base = 0, gg = g;
#pragma unroll
            for (int bit = 0; bit < 14; ++bit)
                if (!((mask >> bit) & 1)) { base |= (gg & 1) << bit; gg >>= 1; }
            int off[16]; float2 a[16];
#pragma unroll
            for (int e = 0; e < 16; e++) {
                int idx = base | (((e >> 3) & 1) << B3) | (((e >> 2) & 1) << B2)
                               | (((e >> 1) & 1) << B1) | ((e & 1) << B0);
                off[e] = sphys(idx); a[e] = S[off[e]];
            }
            ryg<3, 16>(a, c0, s0);    // RY(p0) wire i
            cng<3, 1, 16>(a);         // CNOT(i, i+3)
            ryg<1, 16>(a, c1, s1);    // RY(p1) wire i+3
            ryg<2, 16>(a, c2, s2);    // RY(p2) wire i+1
            cng<2, 0, 16>(a);         // CNOT(i+1, i+4)
            cng<1, 2, 16>(a);         // CNOT(i+3, i+1)
            rxg<0, 16>(a, c3, s3);    // RX(p3) wire i+4
            rxg<2, 16>(a, c4, s4);    // RX(p4) wire i+1
#pragma unroll
            for (int e = 0; e < 16; e++) S[off[e]] = a[e];
        }
        __syncthreads();
    }

    // ---- iteration 11 partial (wires 11,12,14 local; rest deferred to k2) ----
    for (int g = tid; g < 2048; g += NT1) {
        const int mask = (1 << 3) | (1 << 2) | (1 << 0);
        int base = 0, gg = g;
#pragma unroll
        for (int bit = 0; bit < 14; ++bit)
            if (!((mask >> bit) & 1)) { base |= (gg & 1) << bit; gg >>= 1; }
        int off[8]; float2 a[8];
#pragma unroll
        for (int e = 0; e < 8; e++) {
            int idx = base | (((e >> 2) & 1) << 3) | (((e >> 1) & 1) << 2) | (e & 1);
            off[e] = sphys(idx); a[e] = S[off[e]];
        }
        ryg<2, 8>(a, c0, s0);     // RY(p0) wire 11
        cng<2, 0, 8>(a);          // CNOT(11,14)
        ryg<0, 8>(a, c1, s1);     // RY(p1) wire 14
        ryg<1, 8>(a, c2, s2);     // RY(p2) wire 12
#pragma unroll
        for (int e = 0; e < 8; e++) S[off[e]] = a[e];
    }
    __syncthreads();

    // ---- spill sub-state (coalesced) ----
    float2* outp = g_state + (size_t)bi * 16384u;
    for (int j = tid; j < 16384; j += NT1) outp[j] = S[sphys(j)];
}

// ---------------- kernel 2: deferred wire-15 ops + parity-folded measurement ----------------
extern "C" __global__ void __launch_bounds__(256) qsim_k2(const float* __restrict__ kp, K2Args args) {
    int tid = threadIdx.x;
    int bk = blockIdx.x;                 // 0..31 = b*2 + k
    int b = bk >> 1, k = bk & 1;
    float c3, s3, c4, s4;
    {
        float h = 0.5f * kp[k * 5 + 3]; c3 = cosf(h); s3 = sinf(h);
        h = 0.5f * kp[k * 5 + 4];       c4 = cosf(h); s4 = sinf(h);
    }
    const float2* base = g_state + (size_t)bk * 65536u;
    float acc[12];
#pragma unroll
    for (int w = 0; w < 12; w++) acc[w] = 0.f;

    for (int t = tid; t < 4096; t += 256) {
        int b0 = t >> 11, gi = t & 2047;
        const float2* p0 = base + (b0 * 2 + 0) * 16384 + gi * 8;
        const float2* p1 = base + (b0 * 2 + 1) * 16384 + gi * 8;
        // group index e: bit3=wire12, bit2=wire13, bit1=wire14, bit0=wire15
        float2 a[16];
#pragma unroll
        for (int o = 0; o < 8; o++) { a[2 * o] = p0[o]; a[2 * o + 1] = p1[o]; }
        cng<3, 0, 16>(a);           // CNOT(12,15)
        cng<1, 3, 16>(a);           // CNOT(14,12)
        rxg<0, 16>(a, c3, s3);      // RX(p3) wire 15
        rxg<3, 16>(a, c4, s4);      // RX(p4) wire 12
        float pr[16];
#pragma unroll
        for (int e = 0; e < 16; e++) pr[e] = a[e].x * a[e].x + a[e].y * a[e].y;
        int base14 = gi << 3;
#pragma unroll
        for (int w = 0; w < 12; w++) {
            float s = 0.f;
            unsigned sb = args.sbits[w];
#pragma unroll
            for (int e = 0; e < 16; e++) s += ((sb >> e) & 1u) ? -pr[e] : pr[e];
            int par = (__popc(base14 & args.outer14[w]) + (b0 & args.w0f[w])) & 1;
            acc[w] += par ? -s : s;
        }
    }
    // deterministic reduction
#pragma unroll
    for (int w = 0; w < 12; w++)
        for (int o = 16; o > 0; o >>= 1)
            acc[w] += __shfl_xor_sync(0xffffffffu, acc[w], o);
    __shared__ float part[8][12];
    int wid = tid >> 5, lane = tid & 31;
    if (lane == 0) {
#pragma unroll
        for (int w = 0; w < 12; w++) part[wid][w] = acc[w];
    }
    __syncthreads();
    if (tid < 12) {
        float s = 0.f;
#pragma unroll
        for (int r = 0; r < 8; r++) s += part[r][tid];
        g_feats[b * 24 + k * 12 + tid] = s;
    }
}

// ---------------- kernel 3: tiny MLP 24->128->64->4 ----------------
extern "C" __global__ void __launch_bounds__(128) qsim_k3(
    const float* __restrict__ w1, const float* __restrict__ bb1,
    const float* __restrict__ w2, const float* __restrict__ bb2,
    const float* __restrict__ w3, const float* __restrict__ bb3,
    float* __restrict__ out)
{
    __shared__ float f[16 * 24];
    __shared__ float h1[16 * 128];
    __shared__ float h2[16 * 64];
    int tid = threadIdx.x;
    for (int j = tid; j < 384; j += 128) f[j] = g_feats[j];
    __syncthreads();
    {
        int j = tid;                      // one fc1 unit per thread
        float wr[24];
#pragma unroll
        for (int i = 0; i < 24; i++) wr[i] = w1[j * 24 + i];
        float bj = bb1[j];
        for (int bb = 0; bb < 16; bb++) {
            float s = bj;
#pragma unroll
            for (int i = 0; i < 24; i++) s += wr[i] * f[bb * 24 + i];
            h1[bb * 128 + j] = fmaxf(s, 0.f);
        }
    }
    __syncthreads();
    if (tid < 64) {
        float bj = bb2[tid];
        for (int bb = 0; bb < 16; bb++) {
            float s = bj;
            for (int i = 0; i < 128; i++) s += w2[tid * 128 + i] * h1[bb * 128 + i];
            h2[bb * 64 + tid] = fmaxf(s, 0.f);
        }
    }
    __syncthreads();
    if (tid < 64) {
        int bb = tid >> 2, o = tid & 3;
        float s = bb3[o];
        for (int i = 0; i < 64; i++) s += w3[o * 64 + i] * h2[bb * 64 + i];
        out[bb * 4 + o] = s;
    }
}

// ---------------- host launcher ----------------
extern "C" void kernel_launch(void* const* d_in, const int* in_sizes, int n_in,
                              void* d_out, int out_size)
{
    const float* x  = (const float*)d_in[0];
    const float* kp = (const float*)d_in[1];
    const float* w1 = (const float*)d_in[2];
    const float* b1 = (const float*)d_in[3];
    const float* w2 = (const float*)d_in[4];
    const float* b2 = (const float*)d_in[5];
    const float* w3 = (const float*)d_in[6];
    const float* b3 = (const float*)d_in[7];
    float* out = (float*)d_out;

    cudaFuncSetAttribute(qsim_k1, cudaFuncAttributeMaxDynamicSharedMemorySize, 131072);

    // Fold the final 36-CNOT cascade into Pauli-Z parity masks (Heisenberg picture).
    K2Args args;
    int cs[36], ts[36], n = 0;
    for (int i = 0; i < 12; i++) {
        cs[n] = i + 1; ts[n] = i; n++;
        cs[n] = i + 3; ts[n] = i; n++;
        cs[n] = i + 4; ts[n] = i; n++;
    }
    for (int w = 0; w < 12; w++) {
        unsigned m = 1u << w;                        // wire-space mask (bit w = wire w)
        for (int j = 35; j >= 0; --j)
            if ((m >> ts[j]) & 1u) m ^= 1u << cs[j];
        unsigned inner = 0, outer = 0, w0f = m & 1u;
        for (int ww = 1; ww <= 11; ++ww)
            if ((m >> ww) & 1u) outer |= 1u << (14 - ww);   // idx14 bit = 14 - wire
        for (int ww = 12; ww <= 15; ++ww)
            if ((m >> ww) & 1u) inner |= 1u << (15 - ww);   // e bit = 15 - wire
        unsigned sb = 0;
        for (int e = 0; e < 16; e++) {
            unsigned v = (unsigned)e & inner, p = 0;
            while (v) { p ^= 1u; v &= v - 1u; }
            if (p) sb |= 1u << e;
        }
        args.sbits[w] = sb; args.outer14[w] = outer; args.w0f[w] = w0f;
    }

    qsim_k0<<<1, 256>>>(x);
    qsim_k1<<<128, NT1, 131072>>>(kp);
    qsim_k2<<<32, 256>>>(kp, args);
    qsim_k3<<<1, 128>>>(w1, b1, w2, b2, w3, b3, out);
}

// round 4
// speedup vs baseline: 2.2334x; 2.2334x over previous
#include <cuda_runtime.h>
#include <math.h>

#define NT1 512

// Scratch (static device arrays — no allocation)
__device__ float2 g_state[32u * 65536u];   // 16 MB: [b][k][b0][b15][idx14]
__device__ float  g_xd[256];               // pooled inputs: [b][16]
__device__ float  g_feats[16 * 24];        // quantum features

struct K2Args {
    unsigned sbits[12];     // 16-bit sign pattern over group index e
    unsigned outer14[12];   // parity mask over idx14 bits 3..13 (wires 1..11)
    unsigned w0f[12];       // does mask include wire 0?
};

__device__ __forceinline__ int sphys(int idx) { return idx ^ ((idx >> 5) & 0xF); }

template<int T, int N>
__device__ __forceinline__ void ryg(float2* a, float c, float s) {
#pragma unroll
    for (int m = 0; m < N; m++) {
        if (m & (1 << T)) continue;
        int u = m, v = m | (1 << T);
        float2 au = a[u], av = a[v];
        a[u].x = c * au.x - s * av.x;  a[u].y = c * au.y - s * av.y;
        a[v].x = s * au.x + c * av.x;  a[v].y = s * au.y + c * av.y;
    }
}
template<int T, int N>
__device__ __forceinline__ void rxg(float2* a, float c, float s) {
#pragma unroll
    for (int m = 0; m < N; m++) {
        if (m & (1 << T)) continue;
        int u = m, v = m | (1 << T);
        float2 au = a[u], av = a[v];
        // RX: [[c, -is],[-is, c]]
        a[u].x = c * au.x + s * av.y;  a[u].y = c * au.y - s * av.x;
        a[v].x = c * av.x + s * au.y;  a[v].y = c * av.y - s * au.x;
    }
}
template<int C, int T, int N>
__device__ __forceinline__ void cng(float2* a) {
#pragma unroll
    for (int m = 0; m < N; m++) {
        if (!(m & (1 << C)) || (m & (1 << T))) continue;
        int v = m | (1 << T);
        float2 t = a[m]; a[m] = a[v]; a[v] = t;
    }
}

// ---------------- kernel 0: 7x7 avg pooling -> g_xd ----------------
extern "C" __global__ void qsim_k0(const float* __restrict__ x) {
    int t = threadIdx.x;            // 256 threads: b*16 + cell
    int b = t >> 4, cell = t & 15;
    int r = cell >> 2, c = cell & 3;
    const float* px = x + b * 784 + r * 7 * 28 + c * 7;
    float s = 0.f;
    for (int u = 0; u < 7; u++)
#pragma unroll
        for (int v = 0; v < 7; v++) s += px[u * 28 + v];
    g_xd[t] = s * (1.f / 49.f);
}

// ---------------- kernel 1: 14-qubit smem-resident simulation ----------------
// 128 blocks: bi = ((b*2 + k)*2 + b0)*2 + b15. Each holds the 2^14-amp
// sub-statevector (wire0/wire15 bits fixed) and runs the conv block up to
// (but excluding) CNOT(12,15) of iteration 11.
extern "C" __global__ void __launch_bounds__(NT1) qsim_k1(const float* __restrict__ kp) {
    extern __shared__ float2 S[];        // 16384 amps (XOR-swizzled layout)
    __shared__ float tws[16][2];
    __shared__ float ptrig[5][2];
    int tid = threadIdx.x;
    int bi = blockIdx.x;
    int b = bi >> 3, k = (bi >> 2) & 1, bb0 = (bi >> 1) & 1, bb15 = bi & 1;

    if (tid < 16) {
        float ang = g_xd[b * 16 + tid];
        if (tid == 0) ang += kp[k * 5];      // fold iter-0 RY(p0) into encoder on wire 0
        float h = 0.5f * ang;
        tws[tid][0] = cosf(h); tws[tid][1] = sinf(h);
    }
    if (tid < 5) {
        float h = 0.5f * kp[k * 5 + tid];
        ptrig[tid][0] = cosf(h); ptrig[tid][1] = sinf(h);
    }
    __syncthreads();

    float c0 = ptrig[0][0], s0 = ptrig[0][1];
    float c1 = ptrig[1][0], s1 = ptrig[1][1];
    float c2 = ptrig[2][0], s2 = ptrig[2][1];
    float c3 = ptrig[3][0], s3 = ptrig[3][1];
    float c4 = ptrig[4][0], s4 = ptrig[4][1];

    // ---- init: product state (encoder folded; CNOT(0,3) folded as table swap) ----
    {
        float A = tws[0][bb0] * tws[15][bb15];
        float tc[14], ts[14];
#pragma unroll
        for (int w = 1; w <= 14; ++w) { tc[w - 1] = tws[w][0]; ts[w - 1] = tws[w][1]; }
        if (bb0) { float t = tc[2]; tc[2] = ts[2]; ts[2] = t; }   // X on wire 3 when wire0==1
        for (int j = tid; j < 16384; j += NT1) {
            float p = A;
#pragma unroll
            for (int w = 1; w <= 14; ++w)
                p *= ((j >> (14 - w)) & 1) ? ts[w - 1] : tc[w - 1];
            S[sphys(j)] = make_float2(p, 0.f);
        }
    }
    __syncthreads();

    // ---- iteration 0 (wires 1,3,4 local; wire-0 ops folded) ----
    for (int g = tid; g < 2048; g += NT1) {
        const int mask = (1 << 13) | (1 << 11) | (1 << 10);
        int base = 0, gg = g;
#pragma unroll
        for (int bit = 0; bit < 14; ++bit)
            if (!((mask >> bit) & 1)) { base |= (gg & 1) << bit; gg >>= 1; }
        int off[8]; float2 a[8];
#pragma unroll
        for (int e = 0; e < 8; e++) {
            int idx = base | (((e >> 2) & 1) << 13) | (((e >> 1) & 1) << 11) | ((e & 1) << 10);
            off[e] = sphys(idx); a[e] = S[off[e]];
        }
        ryg<1, 8>(a, c1, s1);     // RY(p1) wire 3
        ryg<2, 8>(a, c2, s2);     // RY(p2) wire 1
        cng<2, 0, 8>(a);          // CNOT(1,4)
        cng<1, 2, 8>(a);          // CNOT(3,1)
        rxg<0, 8>(a, c3, s3);     // RX(p3) wire 4
        rxg<2, 8>(a, c4, s4);     // RX(p4) wire 1
#pragma unroll
        for (int e = 0; e < 8; e++) S[off[e]] = a[e];
    }
    __syncthreads();

    // ---- iterations 1..10 (generic 4-bit group: wires i,i+1,i+3,i+4) ----
    for (int i = 1; i <= 10; i++) {
        int B3 = 14 - i, B2 = 13 - i, B1 = 11 - i, B0 = 10 - i;
        int mask = (1 << B3) | (1 << B2) | (1 << B1) | (1 << B0);
        for (int g = tid; g < 1024; g += NT1) {
            int base = 0, gg = g;
#pragma unroll
            for (int bit = 0; bit < 14; ++bit)
                if (!((mask >> bit) & 1)) { base |= (gg & 1) << bit; gg >>= 1; }
            int off[16]; float2 a[16];
#pragma unroll
            for (int e = 0; e < 16; e++) {
                int idx = base | (((e >> 3) & 1) << B3) | (((e >> 2) & 1) << B2)
                               | (((e >> 1) & 1) << B1) | ((e & 1) << B0);
                off[e] = sphys(idx); a[e] = S[off[e]];
            }
            ryg<3, 16>(a, c0, s0);    // RY(p0) wire i
            cng<3, 1, 16>(a);         // CNOT(i, i+3)
            ryg<1, 16>(a, c1, s1);    // RY(p1) wire i+3
            ryg<2, 16>(a, c2, s2);    // RY(p2) wire i+1
            cng<2, 0, 16>(a);         // CNOT(i+1, i+4)
            cng<1, 2, 16>(a);         // CNOT(i+3, i+1)
            rxg<0, 16>(a, c3, s3);    // RX(p3) wire i+4
            rxg<2, 16>(a, c4, s4);    // RX(p4) wire i+1
#pragma unroll
            for (int e = 0; e < 16; e++) S[off[e]] = a[e];
        }
        __syncthreads();
    }

    // ---- iteration 11 partial (wires 11,12,14 local; rest deferred to k2) ----
    for (int g = tid; g < 2048; g += NT1) {
        const int mask = (1 << 3) | (1 << 2) | (1 << 0);
        int base = 0, gg = g;
#pragma unroll
        for (int bit = 0; bit < 14; ++bit)
            if (!((mask >> bit) & 1)) { base |= (gg & 1) << bit; gg >>= 1; }
        int off[8]; float2 a[8];
#pragma unroll
        for (int e = 0; e < 8; e++) {
            int idx = base | (((e >> 2) & 1) << 3) | (((e >> 1) & 1) << 2) | (e & 1);
            off[e] = sphys(idx); a[e] = S[off[e]];
        }
        ryg<2, 8>(a, c0, s0);     // RY(p0) wire 11
        cng<2, 0, 8>(a);          // CNOT(11,14)
        ryg<0, 8>(a, c1, s1);     // RY(p1) wire 14
        ryg<1, 8>(a, c2, s2);     // RY(p2) wire 12
#pragma unroll
        for (int e = 0; e < 8; e++) S[off[e]] = a[e];
    }
    __syncthreads();

    // ---- spill sub-state (coalesced) ----
    float2* outp = g_state + (size_t)bi * 16384u;
    for (int j = tid; j < 16384; j += NT1) outp[j] = S[sphys(j)];
}

// ---------------- kernel 2: deferred wire-15 ops + parity-folded measurement ----------------
extern "C" __global__ void __launch_bounds__(256) qsim_k2(const float* __restrict__ kp, K2Args args) {
    int tid = threadIdx.x;
    int bk = blockIdx.x;                 // 0..31 = b*2 + k
    int b = bk >> 1, k = bk & 1;
    float c3, s3, c4, s4;
    {
        float h = 0.5f * kp[k * 5 + 3]; c3 = cosf(h); s3 = sinf(h);
        h = 0.5f * kp[k * 5 + 4];       c4 = cosf(h); s4 = sinf(h);
    }
    const float2* base = g_state + (size_t)bk * 65536u;
    float acc[12];
#pragma unroll
    for (int w = 0; w < 12; w++) acc[w] = 0.f;

    for (int t = tid; t < 4096; t += 256) {
        int b0 = t >> 11, gi = t & 2047;
        const float2* p0 = base + (b0 * 2 + 0) * 16384 + gi * 8;
        const float2* p1 = base + (b0 * 2 + 1) * 16384 + gi * 8;
        // group index e: bit3=wire12, bit2=wire13, bit1=wire14, bit0=wire15
        float2 a[16];
#pragma unroll
        for (int o = 0; o < 8; o++) { a[2 * o] = p0[o]; a[2 * o + 1] = p1[o]; }
        cng<3, 0, 16>(a);           // CNOT(12,15)
        cng<1, 3, 16>(a);           // CNOT(14,12)
        rxg<0, 16>(a, c3, s3);      // RX(p3) wire 15
        rxg<3, 16>(a, c4, s4);      // RX(p4) wire 12
        float pr[16];
#pragma unroll
        for (int e = 0; e < 16; e++) pr[e] = a[e].x * a[e].x + a[e].y * a[e].y;
        int base14 = gi << 3;
#pragma unroll
        for (int w = 0; w < 12; w++) {
            float s = 0.f;
            unsigned sb = args.sbits[w];
#pragma unroll
            for (int e = 0; e < 16; e++) s += ((sb >> e) & 1u) ? -pr[e] : pr[e];
            int par = (__popc(base14 & args.outer14[w]) + (b0 & args.w0f[w])) & 1;
            acc[w] += par ? -s : s;
        }
    }
    // deterministic reduction
#pragma unroll
    for (int w = 0; w < 12; w++)
        for (int o = 16; o > 0; o >>= 1)
            acc[w] += __shfl_xor_sync(0xffffffffu, acc[w], o);
    __shared__ float part[8][12];
    int wid = tid >> 5, lane = tid & 31;
    if (lane == 0) {
#pragma unroll
        for (int w = 0; w < 12; w++) part[wid][w] = acc[w];
    }
    __syncthreads();
    if (tid < 12) {
        float s = 0.f;
#pragma unroll
        for (int r = 0; r < 8; r++) s += part[r][tid];
        g_feats[b * 24 + k * 12 + tid] = s;
    }
}

// ---------------- kernel 3: tiny MLP 24->128->64->4 ----------------
// 16 blocks (one per batch item), 128 threads. All weights staged into smem
// with coalesced global loads; padded strides (25 / 129) keep LDS conflict-free.
// smem float layout (offsets):
//   w1s   [128*25] @ 0       (3200)
//   w2s   [64*129] @ 3200    (8256)
//   w3s   [256]    @ 11456
//   b1s   [128]    @ 11712
//   b2s   [64]     @ 11840
//   b3s   [4]      @ 11904
//   fts   [24]     @ 11908
//   h1    [128]    @ 11936
//   h2    [64]     @ 12064
//   part  [128]    @ 12128
// total 12256 floats = 49024 bytes
#define K3_SMEM_FLOATS 12256
extern "C" __global__ void __launch_bounds__(128) qsim_k3(
    const float* __restrict__ w1, const float* __restrict__ bb1,
    const float* __restrict__ w2, const float* __restrict__ bb2,
    const float* __restrict__ w3, const float* __restrict__ bb3,
    float* __restrict__ out)
{
    extern __shared__ float sm[];
    float* w1s = sm;             // stride 25
    float* w2s = sm + 3200;      // stride 129
    float* w3s = sm + 11456;
    float* b1s = sm + 11712;
    float* b2s = sm + 11840;
    float* b3s = sm + 11904;
    float* fts = sm + 11908;
    float* h1  = sm + 11936;
    float* h2  = sm + 12064;
    float* prt = sm + 12128;

    int tid = threadIdx.x;
    int b = blockIdx.x;

    // ---- stage weights (coalesced global reads) ----
    for (int t = tid; t < 3072; t += 128) w1s[(t / 24) * 25 + (t % 24)] = w1[t];
    for (int t = tid; t < 8192; t += 128) w2s[(t >> 7) * 129 + (t & 127)] = w2[t];
    for (int t = tid; t < 256;  t += 128) w3s[t] = w3[t];
    if (tid < 128) b1s[tid] = bb1[tid];
    if (tid < 64)  b2s[tid] = bb2[tid];
    if (tid < 4)   b3s[tid] = bb3[tid];
    if (tid < 24)  fts[tid] = g_feats[b * 24 + tid];
    __syncthreads();

    // ---- fc1: one output unit per thread ----
    {
        float s = b1s[tid];
        const float* wr = w1s + tid * 25;
#pragma unroll
        for (int i = 0; i < 24; i++) s += wr[i] * fts[i];
        h1[tid] = fmaxf(s, 0.f);
    }
    __syncthreads();

    // ---- fc2: 64 units, 2 threads per unit (split the 128-dot) ----
    {
        int j = tid & 63, h = tid >> 6;
        const float* wr = w2s + j * 129 + h * 64;
        const float* hr = h1 + h * 64;
        float s = 0.f;
#pragma unroll
        for (int i = 0; i < 64; i++) s += wr[i] * hr[i];
        prt[tid] = s;
    }
    __syncthreads();
    if (tid < 64) h2[tid] = fmaxf(b2s[tid] + prt[tid] + prt[tid + 64], 0.f);
    __syncthreads();

    // ---- fc3: one output per warp, warp-shuffle reduce ----
    {
        int o = tid >> 5, l = tid & 31;
        float s = w3s[o * 64 + l] * h2[l] + w3s[o * 64 + 32 + l] * h2[32 + l];
#pragma unroll
        for (int d = 16; d > 0; d >>= 1) s += __shfl_xor_sync(0xffffffffu, s, d);
        if (l == 0) out[b * 4 + o] = s + b3s[o];
    }
}

// ---------------- host launcher ----------------
extern "C" void kernel_launch(void* const* d_in, const int* in_sizes, int n_in,
                              void* d_out, int out_size)
{
    const float* x  = (const float*)d_in[0];
    const float* kp = (const float*)d_in[1];
    const float* w1 = (const float*)d_in[2];
    const float* b1 = (const float*)d_in[3];
    const float* w2 = (const float*)d_in[4];
    const float* b2 = (const float*)d_in[5];
    const float* w3 = (const float*)d_in[6];
    const float* b3 = (const float*)d_in[7];
    float* out = (float*)d_out;

    cudaFuncSetAttribute(qsim_k1, cudaFuncAttributeMaxDynamicSharedMemorySize, 131072);
    cudaFuncSetAttribute(qsim_k3, cudaFuncAttributeMaxDynamicSharedMemorySize,
                         K3_SMEM_FLOATS * (int)sizeof(float));

    // Fold the final 36-CNOT cascade into Pauli-Z parity masks (Heisenberg picture).
    K2Args args;
    int cs[36], ts[36], n = 0;
    for (int i = 0; i < 12; i++) {
        cs[n] = i + 1; ts[n] = i; n++;
        cs[n] = i + 3; ts[n] = i; n++;
        cs[n] = i + 4; ts[n] = i; n++;
    }
    for (int w = 0; w < 12; w++) {
        unsigned m = 1u << w;                        // wire-space mask (bit w = wire w)
        for (int j = 35; j >= 0; --j)
            if ((m >> ts[j]) & 1u) m ^= 1u << cs[j];
        unsigned inner = 0, outer = 0, w0f = m & 1u;
        for (int ww = 1; ww <= 11; ++ww)
            if ((m >> ww) & 1u) outer |= 1u << (14 - ww);   // idx14 bit = 14 - wire
        for (int ww = 12; ww <= 15; ++ww)
            if ((m >> ww) & 1u) inner |= 1u << (15 - ww);   // e bit = 15 - wire
        unsigned sb = 0;
        for (int e = 0; e < 16; e++) {
            unsigned v = (unsigned)e & inner, p = 0;
            while (v) { p ^= 1u; v &= v - 1u; }
            if (p) sb |= 1u << e;
        }
        args.sbits[w] = sb; args.outer14[w] = outer; args.w0f[w] = w0f;
    }

    qsim_k0<<<1, 256>>>(x);
    qsim_k1<<<128, NT1, 131072>>>(kp);
    qsim_k2<<<32, 256>>>(kp, args);
    qsim_k3<<<16, 128, K3_SMEM_FLOATS * (int)sizeof(float)>>>(w1, b1, w2, b2, w3, b3, out);
}

// round 6
// speedup vs baseline: 2.7132x; 1.2149x over previous
#include <cuda_runtime.h>
#include <math.h>

#define NT1 512

typedef unsigned long long u64;

// Scratch (static device arrays — no allocation)
__device__ u64   g_state[32u * 65536u];   // 16 MB: [b][k][b0][b15][idx14], packed (re,im)
__device__ float g_feats[16 * 24];        // quantum features

// ---------------- f32x2 packed helpers (sm_103a) ----------------
__device__ __forceinline__ u64 pk2(float x, float y) {
    u64 r; asm("mov.b64 %0, {%1,%2};" : "=l"(r) : "f"(x), "f"(y)); return r;
}
__device__ __forceinline__ u64 f2mul(u64 a, u64 b) {
    u64 d; asm("mul.rn.f32x2 %0, %1, %2;" : "=l"(d) : "l"(a), "l"(b)); return d;
}
__device__ __forceinline__ u64 f2fma(u64 a, u64 b, u64 c) {
    u64 d; asm("fma.rn.f32x2 %0, %1, %2, %3;" : "=l"(d) : "l"(a), "l"(b), "l"(c)); return d;
}
__device__ __forceinline__ u64 f2swap(u64 a) {
    unsigned lo, hi; asm("mov.b64 {%0,%1}, %2;" : "=r"(lo), "=r"(hi) : "l"(a));
    u64 d; asm("mov.b64 %0, {%1,%2};" : "=l"(d) : "r"(hi), "r"(lo)); return d;
}
__device__ __forceinline__ void upk(u64 a, float& x, float& y) {
    asm("mov.b64 {%0,%1}, %2;" : "=f"(x), "=f"(y) : "l"(a));
}

__device__ __forceinline__ int sphys(int idx) { return idx ^ ((idx >> 5) & 0xF); }

// RY on packed pair: u' = c*u - s*v ; v' = s*u + c*v (elementwise on re/im)
template<int T, int N>
__device__ __forceinline__ void ryg(u64* a, u64 cc, u64 ss, u64 nss) {
#pragma unroll
    for (int m = 0; m < N; m++) {
        if (m & (1 << T)) continue;
        int v = m | (1 << T);
        u64 au = a[m], av = a[v];
        a[m] = f2fma(cc, au, f2mul(nss, av));
        a[v] = f2fma(cc, av, f2mul(ss, au));
    }
}
// RX: u' = c*u + (s,-s)*swap(v) ; v' = c*v + (s,-s)*swap(u)
template<int T, int N>
__device__ __forceinline__ void rxg(u64* a, u64 cc, u64 sp) {
#pragma unroll
    for (int m = 0; m < N; m++) {
        if (m & (1 << T)) continue;
        int v = m | (1 << T);
        u64 au = a[m], av = a[v];
        a[m] = f2fma(cc, au, f2mul(sp, f2swap(av)));
        a[v] = f2fma(cc, av, f2mul(sp, f2swap(au)));
    }
}
template<int C, int T, int N>
__device__ __forceinline__ void cng(u64* a) {
#pragma unroll
    for (int m = 0; m < N; m++) {
        if (!(m & (1 << C)) || (m & (1 << T))) continue;
        int v = m | (1 << T);
        u64 t = a[m]; a[m] = a[v]; a[v] = t;
    }
}

// ---------------- compile-time parity masks for the 36-CNOT cascade ----------------
struct Masks { unsigned inner[12]; unsigned outer14[12]; unsigned w0f[12]; };
__host__ __device__ constexpr Masks compute_masks() {
    Masks M{};
    int cs[36] = {}, ts2[36] = {}; int n = 0;
    for (int i = 0; i < 12; i++) {
        cs[n] = i + 1; ts2[n] = i; n++;
        cs[n] = i + 3; ts2[n] = i; n++;
        cs[n] = i + 4; ts2[n] = i; n++;
    }
    for (int w = 0; w < 12; w++) {
        unsigned m = 1u << w;
        for (int j = 35; j >= 0; --j)
            if ((m >> ts2[j]) & 1u) m ^= 1u << cs[j];
        unsigned inner = 0, outer = 0;
        M.w0f[w] = m & 1u;
        for (int ww = 1; ww <= 11; ++ww)
            if ((m >> ww) & 1u) outer |= 1u << (14 - ww);
        for (int ww = 12; ww <= 15; ++ww)
            if ((m >> ww) & 1u) inner |= 1u << (15 - ww);
        M.inner[w] = inner; M.outer14[w] = outer;
    }
    return M;
}

// ---------------- kernel 1: 14-qubit smem-resident simulation ----------------
// 128 blocks: bi = ((b*2 + k)*2 + b0)*2 + b15. Pooling folded into prologue.
extern "C" __global__ void __launch_bounds__(NT1) qsim_k1(
    const float* __restrict__ x, const float* __restrict__ kp)
{
    extern __shared__ u64 S[];           // 16384 amps (XOR-swizzled)
    __shared__ float tws[16][2];
    __shared__ float ptrig[5][2];
    int tid = threadIdx.x;
    int bi = blockIdx.x;
    int b = bi >> 3, k = (bi >> 2) & 1, bb0 = (bi >> 1) & 1, bb15 = bi & 1;

    if (tid < 16) {
        // fused 7x7 avg pool for cell tid of batch b
        int r = tid >> 2, c = tid & 3;
        const float* px = x + b * 784 + r * 7 * 28 + c * 7;
        float s = 0.f;
#pragma unroll
        for (int u = 0; u < 7; u++)
#pragma unroll
            for (int v = 0; v < 7; v++) s += px[u * 28 + v];
        float ang = s * (1.f / 49.f);
        if (tid == 0) ang += kp[k * 5];      // fold iter-0 RY(p0) on wire 0
        float h = 0.5f * ang;
        tws[tid][0] = cosf(h); tws[tid][1] = sinf(h);
    }
    if (tid < 5) {
        float h = 0.5f * kp[k * 5 + tid];
        ptrig[tid][0] = cosf(h); ptrig[tid][1] = sinf(h);
    }
    __syncthreads();

    float c0 = ptrig[0][0], s0 = ptrig[0][1];
    float c1 = ptrig[1][0], s1 = ptrig[1][1];
    float c2 = ptrig[2][0], s2 = ptrig[2][1];
    float c3 = ptrig[3][0], s3 = ptrig[3][1];
    float c4 = ptrig[4][0], s4 = ptrig[4][1];
    u64 cc0 = pk2(c0, c0), ss0 = pk2(s0, s0), ns0 = pk2(-s0, -s0);
    u64 cc1 = pk2(c1, c1), ss1 = pk2(s1, s1), ns1 = pk2(-s1, -s1);
    u64 cc2 = pk2(c2, c2), ss2 = pk2(s2, s2), ns2 = pk2(-s2, -s2);
    u64 cc3 = pk2(c3, c3), sp3 = pk2(s3, -s3);
    u64 cc4 = pk2(c4, c4), sp4 = pk2(s4, -s4);

    // ---- init: product state (encoder folded; CNOT(0,3) folded as table swap) ----
    {
        float A = tws[0][bb0] * tws[15][bb15];
        float tc[14], ts[14];
#pragma unroll
        for (int w = 1; w <= 14; ++w) { tc[w - 1] = tws[w][0]; ts[w - 1] = tws[w][1]; }
        if (bb0) { float t = tc[2]; tc[2] = ts[2]; ts[2] = t; }   // X on wire 3 when wire0==1
        for (int j = tid; j < 16384; j += NT1) {
            float p = A;
#pragma unroll
            for (int w = 1; w <= 14; ++w)
                p *= ((j >> (14 - w)) & 1) ? ts[w - 1] : tc[w - 1];
            S[sphys(j)] = pk2(p, 0.f);
        }
    }
    __syncthreads();

    // ---- iteration 0 (wires 1,3,4 local; wire-0 ops folded) ----
    for (int g = tid; g < 2048; g += NT1) {
        const int mask = (1 << 13) | (1 << 11) | (1 << 10);
        int base = 0, gg = g;
#pragma unroll
        for (int bit = 0; bit < 14; ++bit)
            if (!((mask >> bit) & 1)) { base |= (gg & 1) << bit; gg >>= 1; }
        int off[8]; u64 a[8];
#pragma unroll
        for (int e = 0; e < 8; e++) {
            int idx = base | (((e >> 2) & 1) << 13) | (((e >> 1) & 1) << 11) | ((e & 1) << 10);
            off[e] = sphys(idx); a[e] = S[off[e]];
        }
        ryg<1, 8>(a, cc1, ss1, ns1);  // RY(p1) wire 3
        ryg<2, 8>(a, cc2, ss2, ns2);  // RY(p2) wire 1
        cng<2, 0, 8>(a);              // CNOT(1,4)
        cng<1, 2, 8>(a);              // CNOT(3,1)
        rxg<0, 8>(a, cc3, sp3);       // RX(p3) wire 4
        rxg<2, 8>(a, cc4, sp4);       // RX(p4) wire 1
#pragma unroll
        for (int e = 0; e < 8; e++) S[off[e]] = a[e];
    }
    __syncthreads();

    // ---- iterations 1..10 (generic 4-bit group: wires i,i+1,i+3,i+4) ----
    for (int i = 1; i <= 10; i++) {
        int B3 = 14 - i, B2 = 13 - i, B1 = 11 - i, B0 = 10 - i;
        int mask = (1 << B3) | (1 << B2) | (1 << B1) | (1 << B0);
        for (int g = tid; g < 1024; g += NT1) {
            int base = 0, gg = g;
#pragma unroll
            for (int bit = 0; bit < 14; ++bit)
                if (!((mask >> bit) & 1)) { base |= (gg & 1) << bit; gg >>= 1; }
            int off[16]; u64 a[16];
#pragma unroll
            for (int e = 0; e < 16; e++) {
                int idx = base | (((e >> 3) & 1) << B3) | (((e >> 2) & 1) << B2)
                               | (((e >> 1) & 1) << B1) | ((e & 1) << B0);
                off[e] = sphys(idx); a[e] = S[off[e]];
            }
            ryg<3, 16>(a, cc0, ss0, ns0);   // RY(p0) wire i
            cng<3, 1, 16>(a);               // CNOT(i, i+3)
            ryg<1, 16>(a, cc1, ss1, ns1);   // RY(p1) wire i+3
            ryg<2, 16>(a, cc2, ss2, ns2);   // RY(p2) wire i+1
            cng<2, 0, 16>(a);               // CNOT(i+1, i+4)
            cng<1, 2, 16>(a);               // CNOT(i+3, i+1)
            rxg<0, 16>(a, cc3, sp3);        // RX(p3) wire i+4
            rxg<2, 16>(a, cc4, sp4);        // RX(p4) wire i+1
#pragma unroll
            for (int e = 0; e < 16; e++) S[off[e]] = a[e];
        }
        __syncthreads();
    }

    // ---- iteration 11 partial (wires 11,12,14 local; rest deferred to k2) ----
    for (int g = tid; g < 2048; g += NT1) {
        const int mask = (1 << 3) | (1 << 2) | (1 << 0);
        int base = 0, gg = g;
#pragma unroll
        for (int bit = 0; bit < 14; ++bit)
            if (!((mask >> bit) & 1)) { base |= (gg & 1) << bit; gg >>= 1; }
        int off[8]; u64 a[8];
#pragma unroll
        for (int e = 0; e < 8; e++) {
            int idx = base | (((e >> 2) & 1) << 3) | (((e >> 1) & 1) << 2) | (e & 1);
            off[e] = sphys(idx); a[e] = S[off[e]];
        }
        ryg<2, 8>(a, cc0, ss0, ns0);  // RY(p0) wire 11
        cng<2, 0, 8>(a);              // CNOT(11,14)
        ryg<0, 8>(a, cc1, ss1, ns1);  // RY(p1) wire 14
        ryg<1, 8>(a, cc2, ss2, ns2);  // RY(p2) wire 12
#pragma unroll
        for (int e = 0; e < 8; e++) S[off[e]] = a[e];
    }
    __syncthreads();

    // ---- spill sub-state (coalesced) ----
    u64* outp = g_state + (size_t)bi * 16384u;
    for (int j = tid; j < 16384; j += NT1) outp[j] = S[sphys(j)];
}

// ---------------- kernel 2: deferred wire-15 ops + WHT-folded measurement ----------------
extern "C" __global__ void __launch_bounds__(512) qsim_k2(const float* __restrict__ kp) {
    constexpr Masks MK = compute_masks();
    int tid = threadIdx.x;
    int bk = blockIdx.x;                 // 0..31 = b*2 + k
    int b = bk >> 1, k = bk & 1;
    u64 cc3, sp3, cc4, sp4;
    {
        float h = 0.5f * kp[k * 5 + 3];
        cc3 = pk2(cosf(h), cosf(h)); sp3 = pk2(sinf(h), -sinf(h));
        h = 0.5f * kp[k * 5 + 4];
        cc4 = pk2(cosf(h), cosf(h)); sp4 = pk2(sinf(h), -sinf(h));
    }
    const u64* base = g_state + (size_t)bk * 65536u;
    float acc[12];
#pragma unroll
    for (int w = 0; w < 12; w++) acc[w] = 0.f;

    for (int t = tid; t < 4096; t += 512) {
        int b0 = t >> 11, gi = t & 2047;
        const u64* p0 = base + (b0 * 2 + 0) * 16384 + gi * 8;
        const u64* p1 = base + (b0 * 2 + 1) * 16384 + gi * 8;
        // group index e: bit3=wire12, bit2=wire13, bit1=wire14, bit0=wire15
        u64 a[16];
#pragma unroll
        for (int o = 0; o < 8; o++) { a[2 * o] = p0[o]; a[2 * o + 1] = p1[o]; }
        cng<3, 0, 16>(a);             // CNOT(12,15)
        cng<1, 3, 16>(a);             // CNOT(14,12)
        rxg<0, 16>(a, cc3, sp3);      // RX(p3) wire 15
        rxg<3, 16>(a, cc4, sp4);      // RX(p4) wire 12
        float pr[16];
#pragma unroll
        for (int e = 0; e < 16; e++) {
            float xr, xi; upk(a[e], xr, xi);
            pr[e] = xr * xr + xi * xi;
        }
        // 4-bit Walsh-Hadamard: pr[m] <- sum_e (-1)^{popc(m&e)} pr[e]
#pragma unroll
        for (int bit = 1; bit < 16; bit <<= 1) {
#pragma unroll
            for (int m = 0; m < 16; m++) {
                if (m & bit) continue;
                float u = pr[m], v = pr[m | bit];
                pr[m] = u + v; pr[m | bit] = u - v;
            }
        }
        int base14 = gi << 3;
#pragma unroll
        for (int w = 0; w < 12; w++) {
            float s = pr[MK.inner[w]];
            int par = (__popc(base14 & MK.outer14[w]) + (b0 & MK.w0f[w])) & 1;
            acc[w] += par ? -s : s;
        }
    }
    // deterministic reduction
#pragma unroll
    for (int w = 0; w < 12; w++)
        for (int o = 16; o > 0; o >>= 1)
            acc[w] += __shfl_xor_sync(0xffffffffu, acc[w], o);
    __shared__ float part[16][12];
    int wid = tid >> 5, lane = tid & 31;
    if (lane == 0) {
#pragma unroll
        for (int w = 0; w < 12; w++) part[wid][w] = acc[w];
    }
    __syncthreads();
    if (tid < 12) {
        float s = 0.f;
#pragma unroll
        for (int r = 0; r < 16; r++) s += part[r][tid];
        g_feats[b * 24 + k * 12 + tid] = s;
    }
}

// ---------------- kernel 3: tiny MLP 24->128->64->4 ----------------
// 16 blocks (one per batch item), 256 threads. Weights staged via float4
// global loads; padded smem strides (25 / 129) keep LDS conflict-free.
#define K3_SMEM_FLOATS 12380
extern "C" __global__ void __launch_bounds__(256) qsim_k3(
    const float* __restrict__ w1, const float* __restrict__ bb1,
    const float* __restrict__ w2, const float* __restrict__ bb2,
    const float* __restrict__ w3, const float* __restrict__ bb3,
    float* __restrict__ out)
{
    extern __shared__ float sm[];
    float* w1s = sm;             // 128 x stride 25  (3200)
    float* w2s = sm + 3200;      // 64 x stride 129  (8256)
    float* w3s = sm + 11456;     // 256
    float* b1s = sm + 11712;     // 128
    float* b2s = sm + 11840;     // 64
    float* b3s = sm + 11904;     // 4
    float* fts = sm + 11908;     // 24
    float* h1  = sm + 11936;     // 128
    float* h2  = sm + 12064;     // 64
    float* prt = sm + 12124;     // 256

    int tid = threadIdx.x;
    int b = blockIdx.x;

    // ---- stage weights (float4 global reads, scalar padded STS) ----
    const float4* w1v = (const float4*)w1;
    for (int t = tid; t < 768; t += 256) {
        float4 v = w1v[t];
        int base = 4 * t, row = base / 24, col = base % 24;
        float* d = w1s + row * 25 + col;
        d[0] = v.x; d[1] = v.y; d[2] = v.z; d[3] = v.w;
    }
    const float4* w2v = (const float4*)w2;
    for (int t = tid; t < 2048; t += 256) {
        float4 v = w2v[t];
        int base = 4 * t, row = base >> 7, col = base & 127;
        float* d = w2s + row * 129 + col;
        d[0] = v.x; d[1] = v.y; d[2] = v.z; d[3] = v.w;
    }
    if (tid < 64) {
        float4 v = ((const float4*)w3)[tid];
        float* d = w3s + 4 * tid;
        d[0] = v.x; d[1] = v.y; d[2] = v.z; d[3] = v.w;
    }
    if (tid < 128) b1s[tid] = bb1[tid];
    if (tid < 64)  b2s[tid] = bb2[tid];
    if (tid < 4)   b3s[tid] = bb3[tid];
    if (tid < 24)  fts[tid] = g_feats[b * 24 + tid];
    __syncthreads();

    // ---- fc1: one output unit per thread (threads 0..127) ----
    if (tid < 128) {
        float s = b1s[tid];
        const float* wr = w1s + tid * 25;
#pragma unroll
        for (int i = 0; i < 24; i++) s += wr[i] * fts[i];
        h1[tid] = fmaxf(s, 0.f);
    }
    __syncthreads();

    // ---- fc2: 64 units, 4 threads per unit (split the 128-dot into 32s) ----
    {
        int j = tid & 63, h = tid >> 6;
        const float* wr = w2s + j * 129 + h * 32;
        const float* hr = h1 + h * 32;
        float s = 0.f;
#pragma unroll
        for (int i = 0; i < 32; i++) s += wr[i] * hr[i];
        prt[tid] = s;
    }
    __syncthreads();
    if (tid < 64)
        h2[tid] = fmaxf(b2s[tid] + prt[tid] + prt[tid + 64] + prt[tid + 128] + prt[tid + 192], 0.f);
    __syncthreads();

    // ---- fc3: one output per warp (threads 0..127), warp-shuffle reduce ----
    if (tid < 128) {
        int o = tid >> 5, l = tid & 31;
        float s = w3s[o * 64 + l] * h2[l] + w3s[o * 64 + 32 + l] * h2[32 + l];
#pragma unroll
        for (int d = 16; d > 0; d >>= 1) s += __shfl_xor_sync(0xffffffffu, s, d);
        if (l == 0) out[b * 4 + o] = s + b3s[o];
    }
}

// ---------------- host launcher ----------------
extern "C" void kernel_launch(void* const* d_in, const int* in_sizes, int n_in,
                              void* d_out, int out_size)
{
    const float* x  = (const float*)d_in[0];
    const float* kp = (const float*)d_in[1];
    const float* w1 = (const float*)d_in[2];
    const float* b1 = (const float*)d_in[3];
    const float* w2 = (const float*)d_in[4];
    const float* b2 = (const float*)d_in[5];
    const float* w3 = (const float*)d_in[6];
    const float* b3 = (const float*)d_in[7];
    float* out = (float*)d_out;

    cudaFuncSetAttribute(qsim_k1, cudaFuncAttributeMaxDynamicSharedMemorySize, 131072);
    cudaFuncSetAttribute(qsim_k3, cudaFuncAttributeMaxDynamicSharedMemorySize,
                         K3_SMEM_FLOATS * (int)sizeof(float));

    qsim_k1<<<128, NT1, 131072>>>(x, kp);
    qsim_k2<<<32, 512>>>(kp);
    qsim_k3<<<16, 256, K3_SMEM_FLOATS * (int)sizeof(float)>>>(w1, b1, w2, b2, w3, b3, out);
}

// round 7
// speedup vs baseline: 2.9058x; 1.0710x over previous
#include <cuda_runtime.h>
#include <math.h>

#define NT1 1024

typedef unsigned long long u64;

// Scratch (static device arrays — no allocation)
__device__ u64   g_state[32u * 65536u];   // 16 MB: [b][k][b0][b15][idx14], packed (re,im)
__device__ float g_feats[16 * 24];        // quantum features

// ---------------- f32x2 packed helpers (sm_103a) ----------------
__device__ __forceinline__ u64 pk2(float x, float y) {
    u64 r; asm("mov.b64 %0, {%1,%2};" : "=l"(r) : "f"(x), "f"(y)); return r;
}
__device__ __forceinline__ u64 f2mul(u64 a, u64 b) {
    u64 d; asm("mul.rn.f32x2 %0, %1, %2;" : "=l"(d) : "l"(a), "l"(b)); return d;
}
__device__ __forceinline__ u64 f2fma(u64 a, u64 b, u64 c) {
    u64 d; asm("fma.rn.f32x2 %0, %1, %2, %3;" : "=l"(d) : "l"(a), "l"(b), "l"(c)); return d;
}
__device__ __forceinline__ u64 f2swap(u64 a) {
    unsigned lo, hi; asm("mov.b64 {%0,%1}, %2;" : "=r"(lo), "=r"(hi) : "l"(a));
    u64 d; asm("mov.b64 %0, {%1,%2};" : "=l"(d) : "r"(hi), "r"(lo)); return d;
}
__device__ __forceinline__ void upk(u64 a, float& x, float& y) {
    asm("mov.b64 {%0,%1}, %2;" : "=f"(x), "=f"(y) : "l"(a));
}

__device__ __forceinline__ int sphys(int idx) { return idx ^ ((idx >> 5) & 0xF); }

// RY on packed pair: u' = c*u - s*v ; v' = s*u + c*v (elementwise on re/im)
template<int T, int N>
__device__ __forceinline__ void ryg(u64* a, u64 cc, u64 ss, u64 nss) {
#pragma unroll
    for (int m = 0; m < N; m++) {
        if (m & (1 << T)) continue;
        int v = m | (1 << T);
        u64 au = a[m], av = a[v];
        a[m] = f2fma(cc, au, f2mul(nss, av));
        a[v] = f2fma(cc, av, f2mul(ss, au));
    }
}
// RX: u' = c*u + (s,-s)*swap(v) ; v' = c*v + (s,-s)*swap(u)
template<int T, int N>
__device__ __forceinline__ void rxg(u64* a, u64 cc, u64 sp) {
#pragma unroll
    for (int m = 0; m < N; m++) {
        if (m & (1 << T)) continue;
        int v = m | (1 << T);
        u64 au = a[m], av = a[v];
        a[m] = f2fma(cc, au, f2mul(sp, f2swap(av)));
        a[v] = f2fma(cc, av, f2mul(sp, f2swap(au)));
    }
}
template<int C, int T, int N>
__device__ __forceinline__ void cng(u64* a) {
#pragma unroll
    for (int m = 0; m < N; m++) {
        if (!(m & (1 << C)) || (m & (1 << T))) continue;
        int v = m | (1 << T);
        u64 t = a[m]; a[m] = a[v]; a[v] = t;
    }
}

// ---------------- compile-time parity masks for the 36-CNOT cascade ----------------
struct Masks { unsigned inner[12]; unsigned outer14[12]; unsigned w0f[12]; };
__host__ __device__ constexpr Masks compute_masks() {
    Masks M{};
    int cs[36] = {}, ts2[36] = {}; int n = 0;
    for (int i = 0; i < 12; i++) {
        cs[n] = i + 1; ts2[n] = i; n++;
        cs[n] = i + 3; ts2[n] = i; n++;
        cs[n] = i + 4; ts2[n] = i; n++;
    }
    for (int w = 0; w < 12; w++) {
        unsigned m = 1u << w;
        for (int j = 35; j >= 0; --j)
            if ((m >> ts2[j]) & 1u) m ^= 1u << cs[j];
        unsigned inner = 0, outer = 0;
        M.w0f[w] = m & 1u;
        for (int ww = 1; ww <= 11; ++ww)
            if ((m >> ww) & 1u) outer |= 1u << (14 - ww);
        for (int ww = 12; ww <= 15; ++ww)
            if ((m >> ww) & 1u) inner |= 1u << (15 - ww);
        M.inner[w] = inner; M.outer14[w] = outer;
    }
    return M;
}

// ---------------- kernel 1: 14-qubit smem-resident simulation ----------------
// 128 blocks: bi = ((b*2 + k)*2 + b0)*2 + b15. Pooling folded into prologue.
// 1024 threads; iteration loop fully unrolled so all bit positions are
// compile-time constants (base/offset math folds to a few LOP3/SHF).
extern "C" __global__ void __launch_bounds__(NT1) qsim_k1(
    const float* __restrict__ x, const float* __restrict__ kp)
{
    extern __shared__ u64 S[];           // 16384 amps (XOR-swizzled)
    __shared__ float tws[16][2];
    __shared__ float ptrig[5][2];
    int tid = threadIdx.x;
    int bi = blockIdx.x;
    int b = bi >> 3, k = (bi >> 2) & 1, bb0 = (bi >> 1) & 1, bb15 = bi & 1;

    if (tid < 16) {
        // fused 7x7 avg pool for cell tid of batch b
        int r = tid >> 2, c = tid & 3;
        const float* px = x + b * 784 + r * 7 * 28 + c * 7;
        float s = 0.f;
#pragma unroll
        for (int u = 0; u < 7; u++)
#pragma unroll
            for (int v = 0; v < 7; v++) s += px[u * 28 + v];
        float ang = s * (1.f / 49.f);
        if (tid == 0) ang += kp[k * 5];      // fold iter-0 RY(p0) on wire 0
        float h = 0.5f * ang;
        tws[tid][0] = cosf(h); tws[tid][1] = sinf(h);
    }
    if (tid < 5) {
        float h = 0.5f * kp[k * 5 + tid];
        ptrig[tid][0] = cosf(h); ptrig[tid][1] = sinf(h);
    }
    __syncthreads();

    float c0 = ptrig[0][0], s0 = ptrig[0][1];
    float c1 = ptrig[1][0], s1 = ptrig[1][1];
    float c2 = ptrig[2][0], s2 = ptrig[2][1];
    float c3 = ptrig[3][0], s3 = ptrig[3][1];
    float c4 = ptrig[4][0], s4 = ptrig[4][1];
    u64 cc0 = pk2(c0, c0), ss0 = pk2(s0, s0), ns0 = pk2(-s0, -s0);
    u64 cc1 = pk2(c1, c1), ss1 = pk2(s1, s1), ns1 = pk2(-s1, -s1);
    u64 cc2 = pk2(c2, c2), ss2 = pk2(s2, s2), ns2 = pk2(-s2, -s2);
    u64 cc3 = pk2(c3, c3), sp3 = pk2(s3, -s3);
    u64 cc4 = pk2(c4, c4), sp4 = pk2(s4, -s4);

    // ---- init: product state (encoder folded; CNOT(0,3) folded as table swap) ----
    {
        float A = tws[0][bb0] * tws[15][bb15];
        float tc[14], ts[14];
#pragma unroll
        for (int w = 1; w <= 14; ++w) { tc[w - 1] = tws[w][0]; ts[w - 1] = tws[w][1]; }
        if (bb0) { float t = tc[2]; tc[2] = ts[2]; ts[2] = t; }   // X on wire 3 when wire0==1
        for (int j = tid; j < 16384; j += NT1) {
            float p = A;
#pragma unroll
            for (int w = 1; w <= 14; ++w)
                p *= ((j >> (14 - w)) & 1) ? ts[w - 1] : tc[w - 1];
            S[sphys(j)] = pk2(p, 0.f);
        }
    }
    __syncthreads();

    // ---- iteration 0 (wires 1,3,4 local; wire-0 ops folded) ----
    for (int g = tid; g < 2048; g += NT1) {
        // mask bits {13,11,10}; non-mask: bits 0..9 and bit 12
        int base = (g & 0x3FF) | ((g >> 10) << 12);
        int off[8]; u64 a[8];
#pragma unroll
        for (int e = 0; e < 8; e++) {
            int idx = base | ((e & 3) << 10) | ((e >> 2) << 13);
            off[e] = sphys(idx); a[e] = S[off[e]];
        }
        ryg<1, 8>(a, cc1, ss1, ns1);  // RY(p1) wire 3
        ryg<2, 8>(a, cc2, ss2, ns2);  // RY(p2) wire 1
        cng<2, 0, 8>(a);              // CNOT(1,4)
        cng<1, 2, 8>(a);              // CNOT(3,1)
        rxg<0, 8>(a, cc3, sp3);       // RX(p3) wire 4
        rxg<2, 8>(a, cc4, sp4);       // RX(p4) wire 1
#pragma unroll
        for (int e = 0; e < 8; e++) S[off[e]] = a[e];
    }
    __syncthreads();

    // ---- iterations 1..10 (generic 4-bit group: wires i,i+1,i+3,i+4) ----
    // FULLY UNROLLED: all masks/shifts become compile-time constants.
#pragma unroll
    for (int i = 1; i <= 10; i++) {
        const int B0 = 10 - i, B2 = 13 - i;
        {
            int g = tid;                 // 1024 groups, 1024 threads
            // non-mask fields: [0,B0) low, bit B0+2, [B0+5,14) high
            int low = g & ((1 << B0) - 1);
            int rest = g >> B0;
            int base = low | ((rest & 1) << (B0 + 2)) | ((rest >> 1) << (B0 + 5));
            int off[16]; u64 a[16];
#pragma unroll
            for (int e = 0; e < 16; e++) {
                int idx = base | ((e & 3) << B0) | ((e >> 2) << B2);
                off[e] = sphys(idx); a[e] = S[off[e]];
            }
            ryg<3, 16>(a, cc0, ss0, ns0);   // RY(p0) wire i      (bit B3)
            cng<3, 1, 16>(a);               // CNOT(i, i+3)
            ryg<1, 16>(a, cc1, ss1, ns1);   // RY(p1) wire i+3    (bit B1)
            ryg<2, 16>(a, cc2, ss2, ns2);   // RY(p2) wire i+1    (bit B2)
            cng<2, 0, 16>(a);               // CNOT(i+1, i+4)
            cng<1, 2, 16>(a);               // CNOT(i+3, i+1)
            rxg<0, 16>(a, cc3, sp3);        // RX(p3) wire i+4    (bit B0)
            rxg<2, 16>(a, cc4, sp4);        // RX(p4) wire i+1
#pragma unroll
            for (int e = 0; e < 16; e++) S[off[e]] = a[e];
        }
        __syncthreads();
    }

    // ---- iteration 11 partial (wires 11,12,14 local; rest deferred to k2) ----
    for (int g = tid; g < 2048; g += NT1) {
        // mask bits {3,2,0}; non-mask: bit 1 and bits 4..13
        int base = ((g & 1) << 1) | ((g >> 1) << 4);
        int off[8]; u64 a[8];
#pragma unroll
        for (int e = 0; e < 8; e++) {
            int idx = base | (((e >> 2) & 1) << 3) | (((e >> 1) & 1) << 2) | (e & 1);
            off[e] = sphys(idx); a[e] = S[off[e]];
        }
        ryg<2, 8>(a, cc0, ss0, ns0);  // RY(p0) wire 11
        cng<2, 0, 8>(a);              // CNOT(11,14)
        ryg<0, 8>(a, cc1, ss1, ns1);  // RY(p1) wire 14
        ryg<1, 8>(a, cc2, ss2, ns2);  // RY(p2) wire 12
#pragma unroll
        for (int e = 0; e < 8; e++) S[off[e]] = a[e];
    }
    __syncthreads();

    // ---- spill sub-state (coalesced) ----
    u64* outp = g_state + (size_t)bi * 16384u;
    for (int j = tid; j < 16384; j += NT1) outp[j] = S[sphys(j)];
}

// ---------------- kernel 2: deferred wire-15 ops + WHT-folded measurement ----------------
extern "C" __global__ void __launch_bounds__(512) qsim_k2(const float* __restrict__ kp) {
    constexpr Masks MK = compute_masks();
    int tid = threadIdx.x;
    int bk = blockIdx.x;                 // 0..31 = b*2 + k
    int b = bk >> 1, k = bk & 1;
    u64 cc3, sp3, cc4, sp4;
    {
        float h = 0.5f * kp[k * 5 + 3];
        cc3 = pk2(cosf(h), cosf(h)); sp3 = pk2(sinf(h), -sinf(h));
        h = 0.5f * kp[k * 5 + 4];
        cc4 = pk2(cosf(h), cosf(h)); sp4 = pk2(sinf(h), -sinf(h));
    }
    const u64* base = g_state + (size_t)bk * 65536u;
    float acc[12];
#pragma unroll
    for (int w = 0; w < 12; w++) acc[w] = 0.f;

    for (int t = tid; t < 4096; t += 512) {
        int b0 = t >> 11, gi = t & 2047;
        const u64* p0 = base + (b0 * 2 + 0) * 16384 + gi * 8;
        const u64* p1 = base + (b0 * 2 + 1) * 16384 + gi * 8;
        // group index e: bit3=wire12, bit2=wire13, bit1=wire14, bit0=wire15
        u64 a[16];
#pragma unroll
        for (int o = 0; o < 8; o++) { a[2 * o] = p0[o]; a[2 * o + 1] = p1[o]; }
        cng<3, 0, 16>(a);             // CNOT(12,15)
        cng<1, 3, 16>(a);             // CNOT(14,12)
        rxg<0, 16>(a, cc3, sp3);      // RX(p3) wire 15
        rxg<3, 16>(a, cc4, sp4);      // RX(p4) wire 12
        float pr[16];
#pragma unroll
        for (int e = 0; e < 16; e++) {
            float xr, xi; upk(a[e], xr, xi);
            pr[e] = xr * xr + xi * xi;
        }
        // 4-bit Walsh-Hadamard: pr[m] <- sum_e (-1)^{popc(m&e)} pr[e]
#pragma unroll
        for (int bit = 1; bit < 16; bit <<= 1) {
#pragma unroll
            for (int m = 0; m < 16; m++) {
                if (m & bit) continue;
                float u = pr[m], v = pr[m | bit];
                pr[m] = u + v; pr[m | bit] = u - v;
            }
        }
        int base14 = gi << 3;
#pragma unroll
        for (int w = 0; w < 12; w++) {
            float s = pr[MK.inner[w]];
            int par = (__popc(base14 & MK.outer14[w]) + (b0 & MK.w0f[w])) & 1;
            acc[w] += par ? -s : s;
        }
    }
    // deterministic reduction
#pragma unroll
    for (int w = 0; w < 12; w++)
        for (int o = 16; o > 0; o >>= 1)
            acc[w] += __shfl_xor_sync(0xffffffffu, acc[w], o);
    __shared__ float part[16][12];
    int wid = tid >> 5, lane = tid & 31;
    if (lane == 0) {
#pragma unroll
        for (int w = 0; w < 12; w++) part[wid][w] = acc[w];
    }
    __syncthreads();
    if (tid < 12) {
        float s = 0.f;
#pragma unroll
        for (int r = 0; r < 16; r++) s += part[r][tid];
        g_feats[b * 24 + k * 12 + tid] = s;
    }
}

// ---------------- kernel 3: tiny MLP 24->128->64->4 ----------------
// 16 blocks (one per batch item), 256 threads. Weights staged via float4
// global loads; padded smem strides (25 / 129) keep LDS conflict-free.
#define K3_SMEM_FLOATS 12380
extern "C" __global__ void __launch_bounds__(256) qsim_k3(
    const float* __restrict__ w1, const float* __restrict__ bb1,
    const float* __restrict__ w2, const float* __restrict__ bb2,
    const float* __restrict__ w3, const float* __restrict__ bb3,
    float* __restrict__ out)
{
    extern __shared__ float sm[];
    float* w1s = sm;             // 128 x stride 25  (3200)
    float* w2s = sm + 3200;      // 64 x stride 129  (8256)
    float* w3s = sm + 11456;     // 256
    float* b1s = sm + 11712;     // 128
    float* b2s = sm + 11840;     // 64
    float* b3s = sm + 11904;     // 4
    float* fts = sm + 11908;     // 24
    float* h1  = sm + 11936;     // 128
    float* h2  = sm + 12064;     // 64
    float* prt = sm + 12124;     // 256

    int tid = threadIdx.x;
    int b = blockIdx.x;

    // ---- stage weights (float4 global reads, scalar padded STS) ----
    const float4* w1v = (const float4*)w1;
    for (int t = tid; t < 768; t += 256) {
        float4 v = w1v[t];
        int base = 4 * t, row = base / 24, col = base % 24;
        float* d = w1s + row * 25 + col;
        d[0] = v.x; d[1] = v.y; d[2] = v.z; d[3] = v.w;
    }
    const float4* w2v = (const float4*)w2;
    for (int t = tid; t < 2048; t += 256) {
        float4 v = w2v[t];
        int base = 4 * t, row = base >> 7, col = base & 127;
        float* d = w2s + row * 129 + col;
        d[0] = v.x; d[1] = v.y; d[2] = v.z; d[3] = v.w;
    }
    if (tid < 64) {
        float4 v = ((const float4*)w3)[tid];
        float* d = w3s + 4 * tid;
        d[0] = v.x; d[1] = v.y; d[2] = v.z; d[3] = v.w;
    }
    if (tid < 128) b1s[tid] = bb1[tid];
    if (tid < 64)  b2s[tid] = bb2[tid];
    if (tid < 4)   b3s[tid] = bb3[tid];
    if (tid < 24)  fts[tid] = g_feats[b * 24 + tid];
    __syncthreads();

    // ---- fc1: one output unit per thread (threads 0..127) ----
    if (tid < 128) {
        float s = b1s[tid];
        const float* wr = w1s + tid * 25;
#pragma unroll
        for (int i = 0; i < 24; i++) s += wr[i] * fts[i];
        h1[tid] = fmaxf(s, 0.f);
    }
    __syncthreads();

    // ---- fc2: 64 units, 4 threads per unit (split the 128-dot into 32s) ----
    {
        int j = tid & 63, h = tid >> 6;
        const float* wr = w2s + j * 129 + h * 32;
        const float* hr = h1 + h * 32;
        float s = 0.f;
#pragma unroll
        for (int i = 0; i < 32; i++) s += wr[i] * hr[i];
        prt[tid] = s;
    }
    __syncthreads();
    if (tid < 64)
        h2[tid] = fmaxf(b2s[tid] + prt[tid] + prt[tid + 64] + prt[tid + 128] + prt[tid + 192], 0.f);
    __syncthreads();

    // ---- fc3: one output per warp (threads 0..127), warp-shuffle reduce ----
    if (tid < 128) {
        int o = tid >> 5, l = tid & 31;
        float s = w3s[o * 64 + l] * h2[l] + w3s[o * 64 + 32 + l] * h2[32 + l];
#pragma unroll
        for (int d = 16; d > 0; d >>= 1) s += __shfl_xor_sync(0xffffffffu, s, d);
        if (l == 0) out[b * 4 + o] = s + b3s[o];
    }
}

// ---------------- host launcher ----------------
extern "C" void kernel_launch(void* const* d_in, const int* in_sizes, int n_in,
                              void* d_out, int out_size)
{
    const float* x  = (const float*)d_in[0];
    const float* kp = (const float*)d_in[1];
    const float* w1 = (const float*)d_in[2];
    const float* b1 = (const float*)d_in[3];
    const float* w2 = (const float*)d_in[4];
    const float* b2 = (const float*)d_in[5];
    const float* w3 = (const float*)d_in[6];
    const float* b3 = (const float*)d_in[7];
    float* out = (float*)d_out;

    cudaFuncSetAttribute(qsim_k1, cudaFuncAttributeMaxDynamicSharedMemorySize, 131072);
    cudaFuncSetAttribute(qsim_k3, cudaFuncAttributeMaxDynamicSharedMemorySize,
                         K3_SMEM_FLOATS * (int)sizeof(float));

    qsim_k1<<<128, NT1, 131072>>>(x, kp);
    qsim_k2<<<32, 512>>>(kp);
    qsim_k3<<<16, 256, K3_SMEM_FLOATS * (int)sizeof(float)>>>(w1, b1, w2, b2, w3, b3, out);
}